// round 14
// baseline (speedup 1.0000x reference)
#include <cuda_runtime.h>
#include <cuda_fp16.h>
#include <math.h>
#include <stdint.h>

#define BB   8
#define WLEN 1000
#define EMB  100
#define CC   50
#define LL   18000

#define WPAD 1024
// H: [b][w][k-halves], 64 halves (128B) per w row; k>=50 and w>=1000 stay zero
__device__ __align__(16) uint32_t g_Hh[BB * WPAD * 32];

// ===========================================================================
// Kernel 1: embedding + conv1d(k=3,same) + tanh -> g_Hh[b][w][k]
// swizzled emb_s: conflict-free LDS/STS
// ===========================================================================
#define CT_W    40
#define CT_ROWS (CT_W + 2)

__device__ __forceinline__ float tanh_fast(float x) {
    float y;
    asm("tanh.approx.f32 %0, %1;" : "=f"(y) : "f"(x));
    return y;
}

__global__ __launch_bounds__(256)
void conv_kernel(const int* __restrict__ x, const float* __restrict__ W_embed,
                 const float* __restrict__ conv_w, const float* __restrict__ conv_b) {
    __shared__ __align__(16) float emb_s[CT_ROWS * 128];
    __shared__ int tok_s[CT_ROWS];
    const int b  = blockIdx.y;
    const int w0 = blockIdx.x * CT_W;
    const int tid = threadIdx.x;

    if (tid < CT_ROWS) {
        int w = w0 - 1 + tid;
        tok_s[tid] = (w >= 0 && w < WLEN) ? x[b * WLEN + w] : -1;
    }
    __syncthreads();
    for (int i = tid; i < CT_ROWS * 25; i += 256) {
        int r = i / 25, g = i - r * 25;
        int t = tok_s[r];
        float4 v = make_float4(0.f, 0.f, 0.f, 0.f);
        if (t >= 0) v = *(const float4*)&W_embed[(long)t * EMB + g * 4];
        *(float4*)&emb_s[(r * 32 + (g ^ ((r >> 2) & 7))) * 4] = v;
    }
    __syncthreads();

    if (tid < 250) {
        const int p = tid / 10, q = tid - p * 10;
        const int wl = q * 4;
        const int sw0 = q & 7, sw1 = (q + 1) & 7;
        const int c0 = 2 * p, c1 = 2 * p + 1;
        float acc[2][4];
        float bias0 = conv_b[c0], bias1 = conv_b[c1];
#pragma unroll
        for (int w = 0; w < 4; w++) { acc[0][w] = bias0; acc[1][w] = bias1; }

        const float4* cw0 = (const float4*)(conv_w + c0 * EMB * 3);
        const float4* cw1 = (const float4*)(conv_w + c1 * EMB * 3);

        for (int g = 0; g < 25; g++) {
            float4 v[6];
#pragma unroll
            for (int r = 0; r < 6; r++) {
                int sw = (r < 4) ? sw0 : sw1;
                v[r] = *(const float4*)&emb_s[((wl + r) * 32 + (g ^ sw)) * 4];
            }
            float4 q0 = cw0[g * 3], q1 = cw0[g * 3 + 1], q2 = cw0[g * 3 + 2];
#pragma unroll
            for (int w = 0; w < 4; w++) {
                acc[0][w] = fmaf(v[w].x, q0.x, acc[0][w]);
                acc[0][w] = fmaf(v[w + 1].x, q0.y, acc[0][w]);
                acc[0][w] = fmaf(v[w + 2].x, q0.z, acc[0][w]);
                acc[0][w] = fmaf(v[w].y, q0.w, acc[0][w]);
                acc[0][w] = fmaf(v[w + 1].y, q1.x, acc[0][w]);
                acc[0][w] = fmaf(v[w + 2].y, q1.y, acc[0][w]);
                acc[0][w] = fmaf(v[w].z, q1.z, acc[0][w]);
                acc[0][w] = fmaf(v[w + 1].z, q1.w, acc[0][w]);
                acc[0][w] = fmaf(v[w + 2].z, q2.x, acc[0][w]);
                acc[0][w] = fmaf(v[w].w, q2.y, acc[0][w]);
                acc[0][w] = fmaf(v[w + 1].w, q2.z, acc[0][w]);
                acc[0][w] = fmaf(v[w + 2].w, q2.w, acc[0][w]);
            }
            q0 = cw1[g * 3]; q1 = cw1[g * 3 + 1]; q2 = cw1[g * 3 + 2];
#pragma unroll
            for (int w = 0; w < 4; w++) {
                acc[1][w] = fmaf(v[w].x, q0.x, acc[1][w]);
                acc[1][w] = fmaf(v[w + 1].x, q0.y, acc[1][w]);
                acc[1][w] = fmaf(v[w + 2].x, q0.z, acc[1][w]);
                acc[1][w] = fmaf(v[w].y, q0.w, acc[1][w]);
                acc[1][w] = fmaf(v[w + 1].y, q1.x, acc[1][w]);
                acc[1][w] = fmaf(v[w + 2].y, q1.y, acc[1][w]);
                acc[1][w] = fmaf(v[w].z, q1.z, acc[1][w]);
                acc[1][w] = fmaf(v[w + 1].z, q1.w, acc[1][w]);
                acc[1][w] = fmaf(v[w + 2].z, q2.x, acc[1][w]);
                acc[1][w] = fmaf(v[w].w, q2.y, acc[1][w]);
                acc[1][w] = fmaf(v[w + 1].w, q2.z, acc[1][w]);
                acc[1][w] = fmaf(v[w + 2].w, q2.w, acc[1][w]);
            }
        }
#pragma unroll
        for (int i = 0; i < 4; i++) {
            __half2 h = __floats2half2_rn(tanh_fast(acc[0][i]), tanh_fast(acc[1][i]));
            g_Hh[((b * WPAD) + w0 + wl + i) * 32 + p] = *(uint32_t*)&h;
        }
    }
}

// ===========================================================================
// Kernel 2: dual GEMM mma.sync fp16 (3x k16 + 1x k8 = K56), ldmatrix loads.
//   128 threads / 4 warps / 128 labels, 5 CTAs/SM.
//   Race-free 3-buffer cp.async ring of 64-w STAGES (2 chunks per buffer):
//   16 sync boundaries, each wrapping 64 MMAs.
// ===========================================================================
#define ROWB 144    // 72 halves per smem row: conflict-free 16B phases

#define MMA_F16(C, A0, A1, A2, A3, B0, B1)                                  \
    asm volatile(                                                           \
        "mma.sync.aligned.m16n8k16.row.col.f32.f16.f16.f32 "                \
        "{%0,%1,%2,%3}, {%4,%5,%6,%7}, {%8,%9}, {%0,%1,%2,%3};"             \
        : "+f"((C)[0]), "+f"((C)[1]), "+f"((C)[2]), "+f"((C)[3])            \
        : "r"(A0), "r"(A1), "r"(A2), "r"(A3), "r"(B0), "r"(B1))

#define MMA_F16K8(C, A0, A1, B0)                                            \
    asm volatile(                                                           \
        "mma.sync.aligned.m16n8k8.row.col.f32.f16.f16.f32 "                 \
        "{%0,%1,%2,%3}, {%4,%5}, {%6}, {%0,%1,%2,%3};"                      \
        : "+f"((C)[0]), "+f"((C)[1]), "+f"((C)[2]), "+f"((C)[3])            \
        : "r"(A0), "r"(A1), "r"(B0))

#define LDSM_X4(R, A)                                                       \
    asm volatile("ldmatrix.sync.aligned.m8n8.x4.shared.b16 "                \
                 "{%0,%1,%2,%3}, [%4];"                                     \
                 : "=r"((R)[0]), "=r"((R)[1]), "=r"((R)[2]), "=r"((R)[3])   \
                 : "r"(A))

#define LDSM_X1(R, A)                                                       \
    asm volatile("ldmatrix.sync.aligned.m8n8.x1.shared.b16 {%0}, [%1];"     \
                 : "=r"(R) : "r"(A))

#define CP_ASYNC16(S, G)                                                    \
    asm volatile("cp.async.cg.shared.global [%0], [%1], 16;"                \
                 :: "r"(S), "l"(G))
#define CP_COMMIT()  asm volatile("cp.async.commit_group;" ::: "memory")
#define CP_WAIT1()   asm volatile("cp.async.wait_group 1;" ::: "memory")
#define CP_WAIT0()   asm volatile("cp.async.wait_group 0;" ::: "memory")

__device__ __forceinline__ uint32_t packh2(float lo, float hi) {
    __half2 h = __floats2half2_rn(lo, hi);
    return *(uint32_t*)&h;
}
__device__ __forceinline__ float ex2f(float x) {
    float y;
    asm("ex2.approx.f32 %0, %1;" : "=f"(y) : "f"(x));
    return y;
}
__device__ __forceinline__ uint32_t cvta_smem(const void* p) {
    uint32_t a;
    asm("{ .reg .u64 t; cvta.to.shared.u64 t, %1; cvt.u32.u64 %0, t; }"
        : "=r"(a) : "l"(p));
    return a;
}

__device__ __forceinline__ void compute_chunk(
    uint32_t sld, const uint32_t uA[3][4], const uint32_t oA[3][4],
    const uint32_t uA3[2], const uint32_t oA3[2],
    float dacc[2], float nacc[2]) {
    float sacc[4][4], pacc[4][4];
#pragma unroll
    for (int nf = 0; nf < 4; nf++)
#pragma unroll
        for (int c = 0; c < 4; c++) { sacc[nf][c] = 0.f; pacc[nf][c] = 0.f; }

#pragma unroll
    for (int ks = 0; ks < 3; ks++) {
        uint32_t b0v[4], b1v[4];
        LDSM_X4(b0v, sld + ks * 32);
        LDSM_X4(b1v, sld + ks * 32 + 16);
#pragma unroll
        for (int nf = 0; nf < 4; nf++) {
            MMA_F16(sacc[nf], uA[ks][0], uA[ks][1], uA[ks][2], uA[ks][3],
                    b0v[nf], b1v[nf]);
            MMA_F16(pacc[nf], oA[ks][0], oA[ks][1], oA[ks][2], oA[ks][3],
                    b0v[nf], b1v[nf]);
        }
    }
    {
        uint32_t bt[4];
        LDSM_X4(bt, sld + 96);
#pragma unroll
        for (int nf = 0; nf < 4; nf++) {
            MMA_F16K8(sacc[nf], uA3[0], uA3[1], bt[nf]);
            MMA_F16K8(pacc[nf], oA3[0], oA3[1], bt[nf]);
        }
    }
#pragma unroll
    for (int nf = 0; nf < 4; nf++)
#pragma unroll
        for (int c = 0; c < 4; c++) {
            float e = ex2f(sacc[nf][c]);
            int r = c >> 1;
            dacc[r] += e;
            nacc[r] = fmaf(e, pacc[nf][c], nacc[r]);
        }
}

__global__ __launch_bounds__(128, 5)
void attn_kernel(const float* __restrict__ u_w, const float* __restrict__ out_w,
                 const float* __restrict__ out_b, float* __restrict__ out) {
    __shared__ __align__(16) uint32_t Hs[3][64 * 36];   // 3 x 9216B ring

    const int tid  = threadIdx.x;
    const int b    = blockIdx.y;
    const int l0   = blockIdx.x * 64;
    const int lane = tid & 31;
    const int wid  = tid >> 5;          // 0..3 label groups
    const int gid  = lane >> 2;
    const int tig  = lane & 3;

    // ---- Hoisted A fragments: U pre-scaled by log2(e); K56
    const float LOG2E = 1.4426950408889634f;
    uint32_t uA[3][4], oA[3][4], uA3[2], oA3[2];
#pragma unroll
    for (int ks = 0; ks < 3; ks++)
#pragma unroll
        for (int h = 0; h < 2; h++) {
            int kp = ks * 8 + tig + h * 4;
#pragma unroll
            for (int mo = 0; mo < 2; mo++) {
                int l = l0 + wid * 16 + gid + mo * 8;
                float2 uv = make_float2(0.f, 0.f), ov = make_float2(0.f, 0.f);
                if (l < LL) {
                    uv = *(const float2*)&u_w[l * CC + 2 * kp];
                    ov = *(const float2*)&out_w[l * CC + 2 * kp];
                }
                uA[ks][h * 2 + mo] = packh2(uv.x * LOG2E, uv.y * LOG2E);
                oA[ks][h * 2 + mo] = packh2(ov.x, ov.y);
            }
        }
    {
        int kp = 24 + tig;   // only kp 24 (k48,49) non-zero
#pragma unroll
        for (int mo = 0; mo < 2; mo++) {
            int l = l0 + wid * 16 + gid + mo * 8;
            float u0 = 0.f, u1 = 0.f, o0 = 0.f, o1 = 0.f;
            if (l < LL && kp == 24) {
                u0 = u_w[l * CC + 48]; u1 = u_w[l * CC + 49];
                o0 = out_w[l * CC + 48]; o1 = out_w[l * CC + 49];
            }
            uA3[mo] = packh2(u0 * LOG2E, u1 * LOG2E);
            oA3[mo] = packh2(o0, o1);
        }
    }

    // ---- cp.async loader: 128 threads x 4 x 16B = 64 rows x 128B per STAGE
    const int lrow = tid >> 1;             // 0..63
    const int lseg = (tid & 1) * 4;        // 0 or 4 (each thread: 4 segs)
    const uint32_t* gsrc = g_Hh + (b * WPAD + lrow) * 32 + lseg * 4;
    const uint32_t sb0 = cvta_smem(&Hs[0][0]);
    const uint32_t sb1 = cvta_smem(&Hs[1][0]);
    const uint32_t sb2 = cvta_smem(&Hs[2][0]);
    const uint32_t stoff = lrow * ROWB + lseg * 16;

#define ISSUE_STAGE(s, dbase)                                                \
    do {                                                                     \
        const uint32_t* g_ = gsrc + (s) * 64 * 32;                           \
        uint32_t d_ = (dbase) + stoff;                                       \
        CP_ASYNC16(d_,      g_);                                             \
        CP_ASYNC16(d_ + 16, g_ + 4);                                         \
        CP_ASYNC16(d_ + 32, g_ + 8);                                         \
        CP_ASYNC16(d_ + 48, g_ + 12);                                        \
        CP_COMMIT();                                                         \
    } while (0)

    ISSUE_STAGE(0, sb0);
    ISSUE_STAGE(1, sb1);
    CP_WAIT1();
    __syncthreads();

    float dacc[2] = {0.f, 0.f}, nacc[2] = {0.f, 0.f};

    // ---- main loop: stages 0..14 (x3 unrolled, static ring indices).
    // invariant: at top of sub-iter for stage s (buffer s%3): stages <= s
    // complete; s+1 may be pending; issue s+2 into (s+2)%3.
#pragma unroll 1
    for (int s = 0; s < 15; s += 3) {
        ISSUE_STAGE(s + 2, sb2);
        compute_chunk(sb0 + lane * ROWB, uA, oA, uA3, oA3, dacc, nacc);
        compute_chunk(sb0 + (32 + lane) * ROWB, uA, oA, uA3, oA3, dacc, nacc);
        CP_WAIT1();
        __syncthreads();

        ISSUE_STAGE(s + 3, sb0);
        compute_chunk(sb1 + lane * ROWB, uA, oA, uA3, oA3, dacc, nacc);
        compute_chunk(sb1 + (32 + lane) * ROWB, uA, oA, uA3, oA3, dacc, nacc);
        CP_WAIT1();
        __syncthreads();

        if (s < 12) ISSUE_STAGE(s + 4, sb1);
        compute_chunk(sb2 + lane * ROWB, uA, oA, uA3, oA3, dacc, nacc);
        compute_chunk(sb2 + (32 + lane) * ROWB, uA, oA, uA3, oA3, dacc, nacc);
        CP_WAIT1();
        __syncthreads();
    }
    // stage 15 (buffer 0, issued in last iteration's second sub-iter)
    CP_WAIT0();
    __syncthreads();

    // chunk 30 (rows 0..31): full
    compute_chunk(sb0 + lane * ROWB, uA, oA, uA3, oA3, dacc, nacc);

    // chunk 31 (rows 32..63): valid w = 992..999 -> nf==0 only
    {
        const uint32_t sld = sb0 + (32 + (lane & 7)) * ROWB;
        float s4[4] = {0.f, 0.f, 0.f, 0.f}, p4[4] = {0.f, 0.f, 0.f, 0.f};
#pragma unroll
        for (int ks = 0; ks < 3; ks++) {
            uint32_t b0, b1;
            LDSM_X1(b0, sld + ks * 32);
            LDSM_X1(b1, sld + ks * 32 + 16);
            MMA_F16(s4, uA[ks][0], uA[ks][1], uA[ks][2], uA[ks][3], b0, b1);
            MMA_F16(p4, oA[ks][0], oA[ks][1], oA[ks][2], oA[ks][3], b0, b1);
        }
        uint32_t btl;
        LDSM_X1(btl, sld + 96);
        MMA_F16K8(s4, uA3[0], uA3[1], btl);
        MMA_F16K8(p4, oA3[0], oA3[1], btl);
#pragma unroll
        for (int c = 0; c < 4; c++) {
            float e = ex2f(s4[c]);
            int r = c >> 1;
            dacc[r] += e;
            nacc[r] = fmaf(e, p4[c], nacc[r]);
        }
    }

    // ---- reduce over 4 k-group lanes (different w), sigmoid, store
#pragma unroll
    for (int r = 0; r < 2; r++) {
        dacc[r] += __shfl_xor_sync(0xffffffffu, dacc[r], 1);
        dacc[r] += __shfl_xor_sync(0xffffffffu, dacc[r], 2);
        nacc[r] += __shfl_xor_sync(0xffffffffu, nacc[r], 1);
        nacc[r] += __shfl_xor_sync(0xffffffffu, nacc[r], 2);
    }
    if (tig == 0) {
#pragma unroll
        for (int r = 0; r < 2; r++) {
            int l = l0 + wid * 16 + gid + r * 8;
            if (l < LL) {
                float z = nacc[r] / dacc[r] + out_b[l];
                out[b * LL + l] = 1.f / (1.f + __expf(-z));
            }
        }
    }
}

// ===========================================================================
extern "C" void kernel_launch(void* const* d_in, const int* in_sizes, int n_in,
                              void* d_out, int out_size) {
    const int*   x       = (const int*)  d_in[0];
    const float* W_embed = (const float*)d_in[1];
    const float* conv_w  = (const float*)d_in[2];
    const float* conv_b  = (const float*)d_in[3];
    const float* u_w     = (const float*)d_in[4];
    const float* out_w   = (const float*)d_in[5];
    const float* out_b   = (const float*)d_in[6];
    float* out = (float*)d_out;

    dim3 cgrid(WLEN / CT_W, BB);          // (25, 8)
    conv_kernel<<<cgrid, 256>>>(x, W_embed, conv_w, conv_b);

    dim3 agrid((LL + 63) / 64, BB);       // (282, 8)
    attn_kernel<<<agrid, 128>>>(u_w, out_w, out_b, out);
}

// round 15
// speedup vs baseline: 1.5557x; 1.5557x over previous
#include <cuda_runtime.h>
#include <cuda_fp16.h>
#include <math.h>
#include <stdint.h>

#define BB   8
#define WLEN 1000
#define EMB  100
#define CC   50
#define LL   18000

#define WPAD 1024
// H: [b][w][k-halves], 64 halves (128B) per w row; k>=50 and w>=1000 stay zero
__device__ __align__(16) uint32_t g_Hh[BB * WPAD * 32];

// ===========================================================================
// Kernel 1: embedding + conv1d(k=3,same) + tanh -> g_Hh[b][w][k]
// swizzled emb_s: conflict-free LDS/STS
// ===========================================================================
#define CT_W    40
#define CT_ROWS (CT_W + 2)

__device__ __forceinline__ float tanh_fast(float x) {
    float y;
    asm("tanh.approx.f32 %0, %1;" : "=f"(y) : "f"(x));
    return y;
}

__global__ __launch_bounds__(256)
void conv_kernel(const int* __restrict__ x, const float* __restrict__ W_embed,
                 const float* __restrict__ conv_w, const float* __restrict__ conv_b) {
    __shared__ __align__(16) float emb_s[CT_ROWS * 128];
    __shared__ int tok_s[CT_ROWS];
    const int b  = blockIdx.y;
    const int w0 = blockIdx.x * CT_W;
    const int tid = threadIdx.x;

    if (tid < CT_ROWS) {
        int w = w0 - 1 + tid;
        tok_s[tid] = (w >= 0 && w < WLEN) ? x[b * WLEN + w] : -1;
    }
    __syncthreads();
    for (int i = tid; i < CT_ROWS * 25; i += 256) {
        int r = i / 25, g = i - r * 25;
        int t = tok_s[r];
        float4 v = make_float4(0.f, 0.f, 0.f, 0.f);
        if (t >= 0) v = *(const float4*)&W_embed[(long)t * EMB + g * 4];
        *(float4*)&emb_s[(r * 32 + (g ^ ((r >> 2) & 7))) * 4] = v;
    }
    __syncthreads();

    if (tid < 250) {
        const int p = tid / 10, q = tid - p * 10;
        const int wl = q * 4;
        const int sw0 = q & 7, sw1 = (q + 1) & 7;
        const int c0 = 2 * p, c1 = 2 * p + 1;
        float acc[2][4];
        float bias0 = conv_b[c0], bias1 = conv_b[c1];
#pragma unroll
        for (int w = 0; w < 4; w++) { acc[0][w] = bias0; acc[1][w] = bias1; }

        const float4* cw0 = (const float4*)(conv_w + c0 * EMB * 3);
        const float4* cw1 = (const float4*)(conv_w + c1 * EMB * 3);

        for (int g = 0; g < 25; g++) {
            float4 v[6];
#pragma unroll
            for (int r = 0; r < 6; r++) {
                int sw = (r < 4) ? sw0 : sw1;
                v[r] = *(const float4*)&emb_s[((wl + r) * 32 + (g ^ sw)) * 4];
            }
            float4 q0 = cw0[g * 3], q1 = cw0[g * 3 + 1], q2 = cw0[g * 3 + 2];
#pragma unroll
            for (int w = 0; w < 4; w++) {
                acc[0][w] = fmaf(v[w].x, q0.x, acc[0][w]);
                acc[0][w] = fmaf(v[w + 1].x, q0.y, acc[0][w]);
                acc[0][w] = fmaf(v[w + 2].x, q0.z, acc[0][w]);
                acc[0][w] = fmaf(v[w].y, q0.w, acc[0][w]);
                acc[0][w] = fmaf(v[w + 1].y, q1.x, acc[0][w]);
                acc[0][w] = fmaf(v[w + 2].y, q1.y, acc[0][w]);
                acc[0][w] = fmaf(v[w].z, q1.z, acc[0][w]);
                acc[0][w] = fmaf(v[w + 1].z, q1.w, acc[0][w]);
                acc[0][w] = fmaf(v[w + 2].z, q2.x, acc[0][w]);
                acc[0][w] = fmaf(v[w].w, q2.y, acc[0][w]);
                acc[0][w] = fmaf(v[w + 1].w, q2.z, acc[0][w]);
                acc[0][w] = fmaf(v[w + 2].w, q2.w, acc[0][w]);
            }
            q0 = cw1[g * 3]; q1 = cw1[g * 3 + 1]; q2 = cw1[g * 3 + 2];
#pragma unroll
            for (int w = 0; w < 4; w++) {
                acc[1][w] = fmaf(v[w].x, q0.x, acc[1][w]);
                acc[1][w] = fmaf(v[w + 1].x, q0.y, acc[1][w]);
                acc[1][w] = fmaf(v[w + 2].x, q0.z, acc[1][w]);
                acc[1][w] = fmaf(v[w].y, q0.w, acc[1][w]);
                acc[1][w] = fmaf(v[w + 1].y, q1.x, acc[1][w]);
                acc[1][w] = fmaf(v[w + 2].y, q1.y, acc[1][w]);
                acc[1][w] = fmaf(v[w].z, q1.z, acc[1][w]);
                acc[1][w] = fmaf(v[w + 1].z, q1.w, acc[1][w]);
                acc[1][w] = fmaf(v[w + 2].z, q2.x, acc[1][w]);
                acc[1][w] = fmaf(v[w].w, q2.y, acc[1][w]);
                acc[1][w] = fmaf(v[w + 1].w, q2.z, acc[1][w]);
                acc[1][w] = fmaf(v[w + 2].w, q2.w, acc[1][w]);
            }
        }
#pragma unroll
        for (int i = 0; i < 4; i++) {
            __half2 h = __floats2half2_rn(tanh_fast(acc[0][i]), tanh_fast(acc[1][i]));
            g_Hh[((b * WPAD) + w0 + wl + i) * 32 + p] = *(uint32_t*)&h;
        }
    }
}

// ===========================================================================
// Kernel 2: dual GEMM mma.sync fp16 (3x k16 + 1x k8 = K56), ldmatrix loads.
//   128 threads / 4 warps / 128 labels, 5 CTAs/SM (96-reg regime).
//   Race-free 3-buffer cp.async ring of 32-w chunks, depth-2 prefetch,
//   x3-unrolled loop so buffer selection is static.
// ===========================================================================
#define ROWB 144    // 72 halves per smem row: conflict-free 16B phases

#define MMA_F16(C, A0, A1, A2, A3, B0, B1)                                  \
    asm volatile(                                                           \
        "mma.sync.aligned.m16n8k16.row.col.f32.f16.f16.f32 "                \
        "{%0,%1,%2,%3}, {%4,%5,%6,%7}, {%8,%9}, {%0,%1,%2,%3};"             \
        : "+f"((C)[0]), "+f"((C)[1]), "+f"((C)[2]), "+f"((C)[3])            \
        : "r"(A0), "r"(A1), "r"(A2), "r"(A3), "r"(B0), "r"(B1))

#define MMA_F16K8(C, A0, A1, B0)                                            \
    asm volatile(                                                           \
        "mma.sync.aligned.m16n8k8.row.col.f32.f16.f16.f32 "                 \
        "{%0,%1,%2,%3}, {%4,%5}, {%6}, {%0,%1,%2,%3};"                      \
        : "+f"((C)[0]), "+f"((C)[1]), "+f"((C)[2]), "+f"((C)[3])            \
        : "r"(A0), "r"(A1), "r"(B0))

#define LDSM_X4(R, A)                                                       \
    asm volatile("ldmatrix.sync.aligned.m8n8.x4.shared.b16 "                \
                 "{%0,%1,%2,%3}, [%4];"                                     \
                 : "=r"((R)[0]), "=r"((R)[1]), "=r"((R)[2]), "=r"((R)[3])   \
                 : "r"(A))

#define LDSM_X1(R, A)                                                       \
    asm volatile("ldmatrix.sync.aligned.m8n8.x1.shared.b16 {%0}, [%1];"     \
                 : "=r"(R) : "r"(A))

#define CP_ASYNC16(S, G)                                                    \
    asm volatile("cp.async.cg.shared.global [%0], [%1], 16;"                \
                 :: "r"(S), "l"(G))
#define CP_COMMIT()  asm volatile("cp.async.commit_group;" ::: "memory")
#define CP_WAIT1()   asm volatile("cp.async.wait_group 1;" ::: "memory")
#define CP_WAIT0()   asm volatile("cp.async.wait_group 0;" ::: "memory")

__device__ __forceinline__ uint32_t packh2(float lo, float hi) {
    __half2 h = __floats2half2_rn(lo, hi);
    return *(uint32_t*)&h;
}
__device__ __forceinline__ float ex2f(float x) {
    float y;
    asm("ex2.approx.f32 %0, %1;" : "=f"(y) : "f"(x));
    return y;
}
__device__ __forceinline__ uint32_t cvta_smem(const void* p) {
    uint32_t a;
    asm("{ .reg .u64 t; cvta.to.shared.u64 t, %1; cvt.u32.u64 %0, t; }"
        : "=r"(a) : "l"(p));
    return a;
}

__device__ __forceinline__ void compute_chunk(
    uint32_t sld, const uint32_t uA[3][4], const uint32_t oA[3][4],
    const uint32_t uA3[2], const uint32_t oA3[2],
    float dacc[2], float nacc[2]) {
    float sacc[4][4], pacc[4][4];
#pragma unroll
    for (int nf = 0; nf < 4; nf++)
#pragma unroll
        for (int c = 0; c < 4; c++) { sacc[nf][c] = 0.f; pacc[nf][c] = 0.f; }

#pragma unroll
    for (int ks = 0; ks < 3; ks++) {
        uint32_t b0v[4], b1v[4];
        LDSM_X4(b0v, sld + ks * 32);
        LDSM_X4(b1v, sld + ks * 32 + 16);
#pragma unroll
        for (int nf = 0; nf < 4; nf++) {
            MMA_F16(sacc[nf], uA[ks][0], uA[ks][1], uA[ks][2], uA[ks][3],
                    b0v[nf], b1v[nf]);
            MMA_F16(pacc[nf], oA[ks][0], oA[ks][1], oA[ks][2], oA[ks][3],
                    b0v[nf], b1v[nf]);
        }
    }
    {
        uint32_t bt[4];
        LDSM_X4(bt, sld + 96);
#pragma unroll
        for (int nf = 0; nf < 4; nf++) {
            MMA_F16K8(sacc[nf], uA3[0], uA3[1], bt[nf]);
            MMA_F16K8(pacc[nf], oA3[0], oA3[1], bt[nf]);
        }
    }
#pragma unroll
    for (int nf = 0; nf < 4; nf++)
#pragma unroll
        for (int c = 0; c < 4; c++) {
            float e = ex2f(sacc[nf][c]);
            int r = c >> 1;
            dacc[r] += e;
            nacc[r] = fmaf(e, pacc[nf][c], nacc[r]);
        }
}

__global__ __launch_bounds__(128, 5)
void attn_kernel(const float* __restrict__ u_w, const float* __restrict__ out_w,
                 const float* __restrict__ out_b, float* __restrict__ out) {
    __shared__ __align__(16) uint32_t Hs[3][32 * 36];   // 3 x 4608B ring

    const int tid  = threadIdx.x;
    const int b    = blockIdx.y;
    const int l0   = blockIdx.x * 64;
    const int lane = tid & 31;
    const int wid  = tid >> 5;          // 0..3 label groups
    const int gid  = lane >> 2;
    const int tig  = lane & 3;

    // ---- Hoisted A fragments: U pre-scaled by log2(e); K56
    const float LOG2E = 1.4426950408889634f;
    uint32_t uA[3][4], oA[3][4], uA3[2], oA3[2];
#pragma unroll
    for (int ks = 0; ks < 3; ks++)
#pragma unroll
        for (int h = 0; h < 2; h++) {
            int kp = ks * 8 + tig + h * 4;
#pragma unroll
            for (int mo = 0; mo < 2; mo++) {
                int l = l0 + wid * 16 + gid + mo * 8;
                float2 uv = make_float2(0.f, 0.f), ov = make_float2(0.f, 0.f);
                if (l < LL) {
                    uv = *(const float2*)&u_w[l * CC + 2 * kp];
                    ov = *(const float2*)&out_w[l * CC + 2 * kp];
                }
                uA[ks][h * 2 + mo] = packh2(uv.x * LOG2E, uv.y * LOG2E);
                oA[ks][h * 2 + mo] = packh2(ov.x, ov.y);
            }
        }
    {
        int kp = 24 + tig;   // only kp 24 (k48,49) non-zero
#pragma unroll
        for (int mo = 0; mo < 2; mo++) {
            int l = l0 + wid * 16 + gid + mo * 8;
            float u0 = 0.f, u1 = 0.f, o0 = 0.f, o1 = 0.f;
            if (l < LL && kp == 24) {
                u0 = u_w[l * CC + 48]; u1 = u_w[l * CC + 49];
                o0 = out_w[l * CC + 48]; o1 = out_w[l * CC + 49];
            }
            uA3[mo] = packh2(u0 * LOG2E, u1 * LOG2E);
            oA3[mo] = packh2(o0, o1);
        }
    }

    // ---- cp.async loader: 128 threads x 2 x 16B = 32 rows x 128B per chunk
    const int lrow = tid >> 2;             // 0..31
    const int lseg = (tid & 3) * 2;        // 0,2,4,6 (each thread: 2 segs)
    const uint32_t* gsrc = g_Hh + (b * WPAD + lrow) * 32 + lseg * 4;
    const uint32_t sb0 = cvta_smem(&Hs[0][0]);
    const uint32_t sb1 = cvta_smem(&Hs[1][0]);
    const uint32_t sb2 = cvta_smem(&Hs[2][0]);
    const uint32_t stoff = lrow * ROWB + lseg * 16;

#define ISSUE_CHUNK(s, dbase)                                                \
    do {                                                                     \
        const uint32_t* g_ = gsrc + (s) * 32 * 32;                           \
        uint32_t d_ = (dbase) + stoff;                                       \
        CP_ASYNC16(d_,      g_);                                             \
        CP_ASYNC16(d_ + 16, g_ + 4);                                         \
        CP_COMMIT();                                                         \
    } while (0)

    ISSUE_CHUNK(0, sb0);
    ISSUE_CHUNK(1, sb1);
    CP_WAIT1();
    __syncthreads();

    float dacc[2] = {0.f, 0.f}, nacc[2] = {0.f, 0.f};

    // ---- main loop: chunks 0..29, x3-unrolled (static ring buffer indices)
    // invariant at top of sub-iter for chunk c (buffer c%3):
    //   chunks <= c complete; c+1 may be pending; issue c+2 into (c+2)%3.
#pragma unroll 1
    for (int ch = 0; ch < 30; ch += 3) {
        ISSUE_CHUNK(ch + 2, sb2);
        compute_chunk(sb0 + lane * ROWB, uA, oA, uA3, oA3, dacc, nacc);
        CP_WAIT1();
        __syncthreads();

        ISSUE_CHUNK(ch + 3, sb0);
        compute_chunk(sb1 + lane * ROWB, uA, oA, uA3, oA3, dacc, nacc);
        CP_WAIT1();
        __syncthreads();

        ISSUE_CHUNK(ch + 4, sb1);
        compute_chunk(sb2 + lane * ROWB, uA, oA, uA3, oA3, dacc, nacc);
        CP_WAIT1();
        __syncthreads();
    }
    // after loop: chunks 0..29 computed; chunk 30 (sb0) done, 31 (sb1) pending
    compute_chunk(sb0 + lane * ROWB, uA, oA, uA3, oA3, dacc, nacc);
    CP_WAIT0();
    __syncthreads();

    // ---- chunk 31 (sb1): valid w = 992..999 -> nf==0 only
    {
        const uint32_t sld = sb1 + (lane & 7) * ROWB;
        float s4[4] = {0.f, 0.f, 0.f, 0.f}, p4[4] = {0.f, 0.f, 0.f, 0.f};
#pragma unroll
        for (int ks = 0; ks < 3; ks++) {
            uint32_t b0, b1;
            LDSM_X1(b0, sld + ks * 32);
            LDSM_X1(b1, sld + ks * 32 + 16);
            MMA_F16(s4, uA[ks][0], uA[ks][1], uA[ks][2], uA[ks][3], b0, b1);
            MMA_F16(p4, oA[ks][0], oA[ks][1], oA[ks][2], oA[ks][3], b0, b1);
        }
        uint32_t btl;
        LDSM_X1(btl, sld + 96);
        MMA_F16K8(s4, uA3[0], uA3[1], btl);
        MMA_F16K8(p4, oA3[0], oA3[1], btl);
#pragma unroll
        for (int c = 0; c < 4; c++) {
            float e = ex2f(s4[c]);
            int r = c >> 1;
            dacc[r] += e;
            nacc[r] = fmaf(e, p4[c], nacc[r]);
        }
    }

    // ---- reduce over 4 k-group lanes (different w), sigmoid, store
#pragma unroll
    for (int r = 0; r < 2; r++) {
        dacc[r] += __shfl_xor_sync(0xffffffffu, dacc[r], 1);
        dacc[r] += __shfl_xor_sync(0xffffffffu, dacc[r], 2);
        nacc[r] += __shfl_xor_sync(0xffffffffu, nacc[r], 1);
        nacc[r] += __shfl_xor_sync(0xffffffffu, nacc[r], 2);
    }
    if (tig == 0) {
#pragma unroll
        for (int r = 0; r < 2; r++) {
            int l = l0 + wid * 16 + gid + r * 8;
            if (l < LL) {
                float z = nacc[r] / dacc[r] + out_b[l];
                out[b * LL + l] = 1.f / (1.f + __expf(-z));
            }
        }
    }
}

// ===========================================================================
extern "C" void kernel_launch(void* const* d_in, const int* in_sizes, int n_in,
                              void* d_out, int out_size) {
    const int*   x       = (const int*)  d_in[0];
    const float* W_embed = (const float*)d_in[1];
    const float* conv_w  = (const float*)d_in[2];
    const float* conv_b  = (const float*)d_in[3];
    const float* u_w     = (const float*)d_in[4];
    const float* out_w   = (const float*)d_in[5];
    const float* out_b   = (const float*)d_in[6];
    float* out = (float*)d_out;

    dim3 cgrid(WLEN / CT_W, BB);          // (25, 8)
    conv_kernel<<<cgrid, 256>>>(x, W_embed, conv_w, conv_b);

    dim3 agrid((LL + 63) / 64, BB);       // (282, 8)
    attn_kernel<<<agrid, 128>>>(u_w, out_w, out_b, out);
}